// round 5
// baseline (speedup 1.0000x reference)
#include <cuda_runtime.h>
#include <math.h>

#define BN 512
#define TD 2048
#define SD 768
#define HD 128

typedef unsigned long long ull;

// Scratch (device globals — no allocations allowed)
__device__ float g_tpp[32 * BN * HD];   // teacher proj partials (KLEN=64)
__device__ float g_spp[12 * BN * HD];   // student proj partials
// Transposed U/V: [h][row]
__device__ float g_UtT[HD * BN];
__device__ float g_VtT[HD * BN];
__device__ float g_UsT[HD * BN];
__device__ float g_VsT[HD * BN];
// Partial pre-sigmoid dots: [net*8 + hsplit][BN*BN]  (16 MB)
__device__ float g_pd[16][BN * BN];

// ---- packed f32x2 helpers (sm_100+) --------------------------------------
__device__ __forceinline__ ull pk2(float a, float b) {
    ull r; asm("mov.b64 %0, {%1, %2};" : "=l"(r) : "f"(a), "f"(b)); return r;
}
__device__ __forceinline__ float2 unpk2(ull v) {
    float2 r; asm("mov.b64 {%0, %1}, %2;" : "=f"(r.x), "=f"(r.y) : "l"(v)); return r;
}
__device__ __forceinline__ void fma2(ull &acc, ull a, ull b) {
    asm("fma.rn.f32x2 %0, %1, %2, %0;" : "+l"(acc) : "l"(a), "l"(b));
}
// acc(2 i-lanes) += relu(u_{lo,hi} + v) * w   -- mov-free hybrid:
// 2x FADD + 2x FMNMX + 1x FFMA2 (one pack mov that ptxas folds into pairing)
__device__ __forceinline__ void rhyb(ull &acc, float u_lo, float u_hi,
                                     float v, ull w) {
    asm("{\n\t"
        ".reg .f32 tl, th;\n\t"
        ".reg .b64 t;\n\t"
        "add.f32 tl, %1, %3;\n\t"
        "add.f32 th, %2, %3;\n\t"
        "max.f32 tl, tl, 0f00000000;\n\t"
        "max.f32 th, th, 0f00000000;\n\t"
        "mov.b64 t, {tl, th};\n\t"
        "fma.rn.f32x2 %0, t, %4, %0;\n\t"
        "}"
        : "+l"(acc) : "f"(u_lo), "f"(u_hi), "f"(v), "l"(w));
}

// ---------------------------------------------------------------------------
// Projection GEMM partials. z=0 teacher (32 k-splits), z=1 student (12).
// KLEN=64, KC=32. Block: 32 rows x 128 cols, 128 threads, micro 4r x 8c,
// acc packed over COLUMN pairs (a duplicated, b pairs direct from LDS.128).
// ---------------------------------------------------------------------------
__global__ void __launch_bounds__(128)
proj_gemm(const float* __restrict__ T, const float* __restrict__ Wt,
          const float* __restrict__ S, const float* __restrict__ Ws) {
    const int KC = 32;
    const int XP = 36;
    __shared__ __align__(16) float Xst[KC * XP];      // [k][r] transposed
    __shared__ __align__(16) float Wsm[KC * HD];      // [kk][c]

    int z = blockIdx.z;
    int ky = blockIdx.y;
    const float* X; const float* W; float* out; int ldx;
    if (z == 0) { X = T; W = Wt; ldx = TD; out = g_tpp + ky * (BN * HD); }
    else {
        if (ky >= 12) return;
        X = S; W = Ws; ldx = SD; out = g_spp + ky * (BN * HD);
    }

    int tid = threadIdx.x;        // 128
    int tx = tid & 15;            // cols tx*8..+7
    int ty = tid >> 4;            // rows ty*4..+3
    int row0 = blockIdx.x * 32;
    int k0 = ky * 64;

    ull acc[4][4];                // [colpair q][row m]
#pragma unroll
    for (int q = 0; q < 4; q++)
#pragma unroll
        for (int m = 0; m < 4; m++) acc[q][m] = 0ull;

#pragma unroll
    for (int kc = 0; kc < 64; kc += KC) {
        // stage X tile 32r x 32k transposed (2 float4 LDG -> 8 scalar STS)
#pragma unroll
        for (int t = 0; t < 2; t++) {
            int i4 = tid + t * 128;
            int r = i4 >> 3, k4 = (i4 & 7) * 4;
            float4 v = *reinterpret_cast<const float4*>(
                &X[(row0 + r) * ldx + k0 + kc + k4]);
            Xst[(k4 + 0) * XP + r] = v.x;
            Xst[(k4 + 1) * XP + r] = v.y;
            Xst[(k4 + 2) * XP + r] = v.z;
            Xst[(k4 + 3) * XP + r] = v.w;
        }
        // stage W tile 32k x 128c
#pragma unroll
        for (int t = 0; t < 8; t++) {
            int i4 = tid + t * 128;
            int kk = i4 >> 5, c4 = (i4 & 31) * 4;
            float4 v = *reinterpret_cast<const float4*>(
                &W[(k0 + kc + kk) * HD + c4]);
            *reinterpret_cast<float4*>(&Wsm[kk * HD + c4]) = v;
        }
        __syncthreads();
#pragma unroll 8
        for (int kk = 0; kk < KC; kk++) {
            float4 a4 = *reinterpret_cast<const float4*>(&Xst[kk * XP + ty * 4]);
            ulonglong2 b01 = *reinterpret_cast<const ulonglong2*>(&Wsm[kk * HD + tx * 8]);
            ulonglong2 b23 = *reinterpret_cast<const ulonglong2*>(&Wsm[kk * HD + tx * 8 + 4]);
            ull a0 = pk2(a4.x, a4.x), a1 = pk2(a4.y, a4.y);
            ull a2 = pk2(a4.z, a4.z), a3 = pk2(a4.w, a4.w);
            fma2(acc[0][0], a0, b01.x); fma2(acc[0][1], a1, b01.x);
            fma2(acc[0][2], a2, b01.x); fma2(acc[0][3], a3, b01.x);
            fma2(acc[1][0], a0, b01.y); fma2(acc[1][1], a1, b01.y);
            fma2(acc[1][2], a2, b01.y); fma2(acc[1][3], a3, b01.y);
            fma2(acc[2][0], a0, b23.x); fma2(acc[2][1], a1, b23.x);
            fma2(acc[2][2], a2, b23.x); fma2(acc[2][3], a3, b23.x);
            fma2(acc[3][0], a0, b23.y); fma2(acc[3][1], a1, b23.y);
            fma2(acc[3][2], a2, b23.y); fma2(acc[3][3], a3, b23.y);
        }
        __syncthreads();
    }
#pragma unroll
    for (int m = 0; m < 4; m++) {
        int row = row0 + ty * 4 + m;
        float2 q0 = unpk2(acc[0][m]);
        float2 q1 = unpk2(acc[1][m]);
        float2 q2 = unpk2(acc[2][m]);
        float2 q3 = unpk2(acc[3][m]);
        *reinterpret_cast<float4*>(&out[row * HD + tx * 8]) =
            make_float4(q0.x, q0.y, q1.x, q1.y);
        *reinterpret_cast<float4*>(&out[row * HD + tx * 8 + 4]) =
            make_float4(q2.x, q2.y, q3.x, q3.y);
    }
}

// ---------------------------------------------------------------------------
// Fused: sum proj partials + bias -> smem X, then U/V GEMM through both W1
// halves, outputs TRANSPOSED [h][row]. Also zeroes the output scalar.
// grid (16 rowblocks, 2 nets), 256 threads.
// ---------------------------------------------------------------------------
__global__ void __launch_bounds__(256)
fused_uv(const float* __restrict__ bt, const float* __restrict__ bs,
         const float* __restrict__ W1, const float* __restrict__ b1,
         float* __restrict__ out, int out_size) {
    const int XS = 129;   // Xs stride: bank-conflict-free scalar a-LDS
    __shared__ float Xs[32 * XS];                 // [r][k]
    __shared__ __align__(16) float Wu[16 * HD];   // W1 U-half chunk
    __shared__ __align__(16) float Wv[16 * HD];   // W1 V-half chunk

    int bx = blockIdx.x, by = blockIdx.y;
    int tid = threadIdx.x;

    if (bx == 0 && by == 0 && tid == 0)
        for (int i = 0; i < out_size; i++) out[i] = 0.0f;

    const float* pbase = by ? g_spp : g_tpp;
    int np = by ? 12 : 32;
    const float* bias = by ? bs : bt;
    float* UT = by ? g_UsT : g_UtT;
    float* VT = by ? g_VsT : g_VtT;

    // ---- Phase A: X rows = bias + sum of partials ----
    {
        int r = tid >> 3;
        int c0 = (tid & 7) * 16;
        int rg = bx * 32 + r;
#pragma unroll
        for (int q = 0; q < 4; q++) {
            int c = c0 + q * 4;
            float4 acc = *reinterpret_cast<const float4*>(&bias[c]);
#pragma unroll 4
            for (int p = 0; p < np; p++) {
                float4 v = *reinterpret_cast<const float4*>(
                    &pbase[p * (BN * HD) + rg * HD + c]);
                acc.x += v.x; acc.y += v.y; acc.z += v.z; acc.w += v.w;
            }
            Xs[r * XS + c + 0] = acc.x;
            Xs[r * XS + c + 1] = acc.y;
            Xs[r * XS + c + 2] = acc.z;
            Xs[r * XS + c + 3] = acc.w;
        }
    }

    // ---- Phase B: U = X @ W1[:128], V = X @ W1[128:] ----
    int rowsel = tid & 7;        // rows rowsel*4..+3 (duplicated side)
    int colsel = tid >> 3;       // cols colsel*4..+3 (packed pairs)

    ull acc[2][2][4];            // [mat][colpair][row]
#pragma unroll
    for (int mt = 0; mt < 2; mt++)
#pragma unroll
        for (int p = 0; p < 2; p++)
#pragma unroll
            for (int m = 0; m < 4; m++) acc[mt][p][m] = 0ull;

    for (int kc = 0; kc < HD; kc += 16) {
        __syncthreads();
        // stage W chunks 16k x 128c for both halves (2 float4 each/thread)
#pragma unroll
        for (int t = 0; t < 2; t++) {
            int i4 = tid + t * 256;
            int kk = i4 >> 5, c4 = (i4 & 31) * 4;
            *reinterpret_cast<float4*>(&Wu[kk * HD + c4]) =
                *reinterpret_cast<const float4*>(&W1[(kc + kk) * HD + c4]);
            *reinterpret_cast<float4*>(&Wv[kk * HD + c4]) =
                *reinterpret_cast<const float4*>(&W1[(128 + kc + kk) * HD + c4]);
        }
        __syncthreads();
#pragma unroll 8
        for (int kk = 0; kk < 16; kk++) {
            int k = kc + kk;
            float a0 = Xs[(rowsel * 4 + 0) * XS + k];
            float a1 = Xs[(rowsel * 4 + 1) * XS + k];
            float a2 = Xs[(rowsel * 4 + 2) * XS + k];
            float a3 = Xs[(rowsel * 4 + 3) * XS + k];
            ull ad0 = pk2(a0, a0), ad1 = pk2(a1, a1);
            ull ad2 = pk2(a2, a2), ad3 = pk2(a3, a3);
            ulonglong2 wu = *reinterpret_cast<const ulonglong2*>(&Wu[kk * HD + colsel * 4]);
            ulonglong2 wv = *reinterpret_cast<const ulonglong2*>(&Wv[kk * HD + colsel * 4]);
            fma2(acc[0][0][0], ad0, wu.x); fma2(acc[0][0][1], ad1, wu.x);
            fma2(acc[0][0][2], ad2, wu.x); fma2(acc[0][0][3], ad3, wu.x);
            fma2(acc[0][1][0], ad0, wu.y); fma2(acc[0][1][1], ad1, wu.y);
            fma2(acc[0][1][2], ad2, wu.y); fma2(acc[0][1][3], ad3, wu.y);
            fma2(acc[1][0][0], ad0, wv.x); fma2(acc[1][0][1], ad1, wv.x);
            fma2(acc[1][0][2], ad2, wv.x); fma2(acc[1][0][3], ad3, wv.x);
            fma2(acc[1][1][0], ad0, wv.y); fma2(acc[1][1][1], ad1, wv.y);
            fma2(acc[1][1][2], ad2, wv.y); fma2(acc[1][1][3], ad3, wv.y);
        }
    }

    // ---- Store transposed [h][row] (b1 folded into U only) ----
    int r0g = bx * 32 + rowsel * 4;
#pragma unroll
    for (int cc = 0; cc < 4; cc++) {
        int col = colsel * 4 + cc;
        int p = cc >> 1;
        float bu = b1[col];
        float4 uo, vo;
        {
            float2 h0 = unpk2(acc[0][p][0]);
            float2 h1 = unpk2(acc[0][p][1]);
            float2 h2 = unpk2(acc[0][p][2]);
            float2 h3 = unpk2(acc[0][p][3]);
            if (cc & 1) uo = make_float4(h0.y, h1.y, h2.y, h3.y);
            else        uo = make_float4(h0.x, h1.x, h2.x, h3.x);
        }
        {
            float2 h0 = unpk2(acc[1][p][0]);
            float2 h1 = unpk2(acc[1][p][1]);
            float2 h2 = unpk2(acc[1][p][2]);
            float2 h3 = unpk2(acc[1][p][3]);
            if (cc & 1) vo = make_float4(h0.y, h1.y, h2.y, h3.y);
            else        vo = make_float4(h0.x, h1.x, h2.x, h3.x);
        }
        uo.x += bu; uo.y += bu; uo.z += bu; uo.w += bu;
        *reinterpret_cast<float4*>(&UT[col * BN + r0g]) = uo;
        *reinterpret_cast<float4*>(&VT[col * BN + r0g]) = vo;
    }
}

// ---------------------------------------------------------------------------
// Pairwise partial dots. zz = net*8 + hsplit (16 splits of 16 h each).
// Tile 32(i) x 64(j), 128 threads, micro 4x4; hybrid scalar-add + packed fma.
// ---------------------------------------------------------------------------
__global__ void __launch_bounds__(128)
pairwise_part(const float* __restrict__ w2) {
    const int HC = 16;
    const int US = 36;
    const int VS = 68;
    __shared__ __align__(16) float sU[HC * US];   // [h][i-row]
    __shared__ __align__(16) float sV[HC * VS];   // [h][j-row]
    __shared__ ull swd[HC];

    int zz = blockIdx.z;
    int net = zz >> 3;
    int hc = (zz & 7) * HC;
    const float* UT = net ? g_UsT : g_UtT;
    const float* VT = net ? g_VsT : g_VtT;
    float* pd = g_pd[zz];

    int tid = threadIdx.x;       // 128
    int tx = tid & 15;           // j = jbase + tx*4 + n
    int ty = tid >> 4;           // i = ibase + ty*4 + m
    int jbase = blockIdx.x * 64;
    int ibase = blockIdx.y * 32;

    // stage U tile: [h][r] (coalesced LDG, conflict-free STS)
#pragma unroll
    for (int t = 0; t < 4; t++) {
        int i = tid + t * 128;            // 512: h = i>>5, r = i&31
        int h = i >> 5, r = i & 31;
        sU[h * US + r] = UT[(hc + h) * BN + ibase + r];
    }
#pragma unroll
    for (int t = 0; t < 8; t++) {
        int i = tid + t * 128;            // 1024: h = i>>6, r = i&63
        int h = i >> 6, r = i & 63;
        sV[h * VS + r] = VT[(hc + h) * BN + jbase + r];
    }
    if (tid < HC) { float w = w2[hc + tid]; swd[tid] = pk2(w, w); }
    __syncthreads();

    ull acc[4][2];               // [n][i-pair]
#pragma unroll
    for (int n = 0; n < 4; n++) { acc[n][0] = 0ull; acc[n][1] = 0ull; }

#pragma unroll
    for (int h = 0; h < HC; h++) {
        float4 u4 = *reinterpret_cast<const float4*>(&sU[h * US + ty * 4]);
        float4 v4 = *reinterpret_cast<const float4*>(&sV[h * VS + tx * 4]);
        ull wd = swd[h];
        rhyb(acc[0][0], u4.x, u4.y, v4.x, wd);
        rhyb(acc[0][1], u4.z, u4.w, v4.x, wd);
        rhyb(acc[1][0], u4.x, u4.y, v4.y, wd);
        rhyb(acc[1][1], u4.z, u4.w, v4.y, wd);
        rhyb(acc[2][0], u4.x, u4.y, v4.z, wd);
        rhyb(acc[2][1], u4.z, u4.w, v4.z, wd);
        rhyb(acc[3][0], u4.x, u4.y, v4.w, wd);
        rhyb(acc[3][1], u4.z, u4.w, v4.w, wd);
    }

    float sums[4][4];            // [m][n]
#pragma unroll
    for (int n = 0; n < 4; n++) {
#pragma unroll
        for (int p = 0; p < 2; p++) {
            float2 v = unpk2(acc[n][p]);
            sums[p * 2 + 0][n] = v.x;
            sums[p * 2 + 1][n] = v.y;
        }
    }
#pragma unroll
    for (int m = 0; m < 4; m++) {
        int i = ibase + ty * 4 + m;
        *reinterpret_cast<float4*>(&pd[i * BN + jbase + tx * 4]) =
            make_float4(sums[m][0], sums[m][1], sums[m][2], sums[m][3]);
    }
}

// ---------------------------------------------------------------------------
// Reduce: rel = sigmoid(sum of 8 h-partials + b2) per net, diag skipped,
// MSE atomically accumulated into out (zeroed by fused_uv).
// ---------------------------------------------------------------------------
__global__ void __launch_bounds__(256)
reduce_kernel(const float* __restrict__ b2v, float* __restrict__ out) {
    __shared__ float sred[256];
    int g = blockIdx.x * 256 + threadIdx.x;     // 65536 groups of 4
    int i = g >> 7;
    int j0 = (g & 127) * 4;
    float b2 = b2v[0];

    float4 t = make_float4(0.f, 0.f, 0.f, 0.f);
    float4 s = make_float4(0.f, 0.f, 0.f, 0.f);
#pragma unroll
    for (int k = 0; k < 8; k++) {
        float4 a = *reinterpret_cast<const float4*>(&g_pd[k][g * 4]);
        t.x += a.x; t.y += a.y; t.z += a.z; t.w += a.w;
        float4 b = *reinterpret_cast<const float4*>(&g_pd[8 + k][g * 4]);
        s.x += b.x; s.y += b.y; s.z += b.z; s.w += b.w;
    }
    float tv[4] = {t.x, t.y, t.z, t.w};
    float sv[4] = {s.x, s.y, s.z, s.w};
    float local = 0.0f;
#pragma unroll
    for (int n = 0; n < 4; n++) {
        if (i == j0 + n) continue;   // diagonal: rel defined 0 in both
        float rt = 1.0f / (1.0f + __expf(-(tv[n] + b2)));
        float rs = 1.0f / (1.0f + __expf(-(sv[n] + b2)));
        float d = rs - rt;
        local = fmaf(d, d, local);
    }

    sred[threadIdx.x] = local;
    __syncthreads();
    for (int st = 128; st > 0; st >>= 1) {
        if (threadIdx.x < st) sred[threadIdx.x] += sred[threadIdx.x + st];
        __syncthreads();
    }
    if (threadIdx.x == 0)
        atomicAdd(out, sred[0] * (1.0f / ((float)BN * (float)BN)));
}

// ---------------------------------------------------------------------------
extern "C" void kernel_launch(void* const* d_in, const int* in_sizes, int n_in,
                              void* d_out, int out_size) {
    const float* teacher = (const float*)d_in[0];
    const float* student = (const float*)d_in[1];
    const float* Wt = (const float*)d_in[2];
    const float* bt = (const float*)d_in[3];
    const float* Wsw = (const float*)d_in[4];
    const float* bs = (const float*)d_in[5];
    const float* W1 = (const float*)d_in[6];
    const float* b1 = (const float*)d_in[7];
    const float* W2 = (const float*)d_in[8];
    const float* b2 = (const float*)d_in[9];
    float* out = (float*)d_out;

    proj_gemm<<<dim3(16, 32, 2), 128>>>(teacher, Wt, student, Wsw);
    fused_uv<<<dim3(16, 2), 256>>>(bt, bs, W1, b1, out, out_size);
    pairwise_part<<<dim3(8, 16, 16), 128>>>(W2);
    reduce_kernel<<<256, 256>>>(b2, out);
}

// round 6
// speedup vs baseline: 1.0814x; 1.0814x over previous
#include <cuda_runtime.h>
#include <math.h>

#define BN 512
#define TD 2048
#define SD 768
#define HD 128

typedef unsigned long long ull;

// Scratch (device globals — no allocations allowed)
__device__ float g_tpp[32 * BN * HD];   // teacher proj partials (KLEN=64)
__device__ float g_spp[12 * BN * HD];   // student proj partials
__device__ float g_tp[BN * HD];
__device__ float g_sp[BN * HD];
// Transposed U/V: [h][row]
__device__ float g_UtT[HD * BN];
__device__ float g_VtT[HD * BN];
__device__ float g_UsT[HD * BN];
__device__ float g_VsT[HD * BN];

// ---- packed f32x2 helpers (sm_100+) --------------------------------------
__device__ __forceinline__ ull pk2(float a, float b) {
    ull r; asm("mov.b64 %0, {%1, %2};" : "=l"(r) : "f"(a), "f"(b)); return r;
}
__device__ __forceinline__ float2 unpk2(ull v) {
    float2 r; asm("mov.b64 {%0, %1}, %2;" : "=f"(r.x), "=f"(r.y) : "l"(v)); return r;
}
__device__ __forceinline__ void fma2(ull &acc, ull a, ull b) {
    asm("fma.rn.f32x2 %0, %1, %2, %0;" : "+l"(acc) : "l"(a), "l"(b));
}
// acc += relu(u + v) * w, fully packed.
// Uses relu(x)*w = (x + |x|) * (w/2); wh must be pre-halved.
// (x+|x|) is exact (0 or 2x), w/2 exact, so result == fl(relu(x)*w).
__device__ __forceinline__ void rabs(ull &acc, ull u, ull v, ull wh) {
    asm("{\n\t"
        ".reg .b64 t, ta;\n\t"
        "add.rn.f32x2 t, %1, %2;\n\t"
        "and.b64 ta, t, 0x7FFFFFFF7FFFFFFF;\n\t"
        "add.rn.f32x2 t, t, ta;\n\t"
        "fma.rn.f32x2 %0, t, %3, %0;\n\t"
        "}"
        : "+l"(acc) : "l"(u), "l"(v), "l"(wh));
}

// ---------------------------------------------------------------------------
// Projection GEMM partials. z=0 teacher (32 k-splits), z=1 student (12).
// KLEN=64, KC=32. Block: 32 rows x 128 cols, 128 threads, micro 4r x 8c.
// Also zeroes the output scalar (block (0,0,0)).
// ---------------------------------------------------------------------------
__global__ void __launch_bounds__(128)
proj_gemm(const float* __restrict__ T, const float* __restrict__ Wt,
          const float* __restrict__ S, const float* __restrict__ Ws,
          float* __restrict__ out, int out_size) {
    const int KC = 32;
    const int XP = 36;
    __shared__ __align__(16) float Xst[KC * XP];      // [k][r] transposed
    __shared__ __align__(16) float Wsm[KC * HD];      // [kk][c]

    if (blockIdx.x == 0 && blockIdx.y == 0 && blockIdx.z == 0 && threadIdx.x == 0)
        for (int i = 0; i < out_size; i++) out[i] = 0.0f;

    int z = blockIdx.z;
    int ky = blockIdx.y;
    const float* X; const float* W; float* outp; int ldx;
    if (z == 0) { X = T; W = Wt; ldx = TD; outp = g_tpp + ky * (BN * HD); }
    else {
        if (ky >= 12) return;
        X = S; W = Ws; ldx = SD; outp = g_spp + ky * (BN * HD);
    }

    int tid = threadIdx.x;        // 128
    int tx = tid & 15;            // cols tx*8..+7
    int ty = tid >> 4;            // rows ty*4..+3
    int row0 = blockIdx.x * 32;
    int k0 = ky * 64;

    ull acc[4][4];                // [colpair q][row m]
#pragma unroll
    for (int q = 0; q < 4; q++)
#pragma unroll
        for (int m = 0; m < 4; m++) acc[q][m] = 0ull;

#pragma unroll
    for (int kc = 0; kc < 64; kc += KC) {
        // stage X tile 32r x 32k transposed
#pragma unroll
        for (int t = 0; t < 2; t++) {
            int i4 = tid + t * 128;
            int r = i4 >> 3, k4 = (i4 & 7) * 4;
            float4 v = *reinterpret_cast<const float4*>(
                &X[(row0 + r) * ldx + k0 + kc + k4]);
            Xst[(k4 + 0) * XP + r] = v.x;
            Xst[(k4 + 1) * XP + r] = v.y;
            Xst[(k4 + 2) * XP + r] = v.z;
            Xst[(k4 + 3) * XP + r] = v.w;
        }
        // stage W tile 32k x 128c
#pragma unroll
        for (int t = 0; t < 8; t++) {
            int i4 = tid + t * 128;
            int kk = i4 >> 5, c4 = (i4 & 31) * 4;
            float4 v = *reinterpret_cast<const float4*>(
                &W[(k0 + kc + kk) * HD + c4]);
            *reinterpret_cast<float4*>(&Wsm[kk * HD + c4]) = v;
        }
        __syncthreads();
#pragma unroll 8
        for (int kk = 0; kk < KC; kk++) {
            float4 a4 = *reinterpret_cast<const float4*>(&Xst[kk * XP + ty * 4]);
            ulonglong2 b01 = *reinterpret_cast<const ulonglong2*>(&Wsm[kk * HD + tx * 8]);
            ulonglong2 b23 = *reinterpret_cast<const ulonglong2*>(&Wsm[kk * HD + tx * 8 + 4]);
            ull a0 = pk2(a4.x, a4.x), a1 = pk2(a4.y, a4.y);
            ull a2 = pk2(a4.z, a4.z), a3 = pk2(a4.w, a4.w);
            fma2(acc[0][0], a0, b01.x); fma2(acc[0][1], a1, b01.x);
            fma2(acc[0][2], a2, b01.x); fma2(acc[0][3], a3, b01.x);
            fma2(acc[1][0], a0, b01.y); fma2(acc[1][1], a1, b01.y);
            fma2(acc[1][2], a2, b01.y); fma2(acc[1][3], a3, b01.y);
            fma2(acc[2][0], a0, b23.x); fma2(acc[2][1], a1, b23.x);
            fma2(acc[2][2], a2, b23.x); fma2(acc[2][3], a3, b23.x);
            fma2(acc[3][0], a0, b23.y); fma2(acc[3][1], a1, b23.y);
            fma2(acc[3][2], a2, b23.y); fma2(acc[3][3], a3, b23.y);
        }
        __syncthreads();
    }
#pragma unroll
    for (int m = 0; m < 4; m++) {
        int row = row0 + ty * 4 + m;
        float2 q0 = unpk2(acc[0][m]);
        float2 q1 = unpk2(acc[1][m]);
        float2 q2 = unpk2(acc[2][m]);
        float2 q3 = unpk2(acc[3][m]);
        *reinterpret_cast<float4*>(&outp[row * HD + tx * 8]) =
            make_float4(q0.x, q0.y, q1.x, q1.y);
        *reinterpret_cast<float4*>(&outp[row * HD + tx * 8 + 4]) =
            make_float4(q2.x, q2.y, q3.x, q3.y);
    }
}

// ---------------------------------------------------------------------------
// Sum proj partials + bias -> g_tp / g_sp. Grid 128 x 256 thr, one float4
// per thread, 4 independent accumulator chains for MLP.
// ---------------------------------------------------------------------------
__global__ void __launch_bounds__(256)
sumtp(const float* __restrict__ bt, const float* __restrict__ bs) {
    int b = blockIdx.x;
    int teacher = (b < 64);
    int i4 = (teacher ? b : b - 64) * 256 + threadIdx.x;   // 0..16383
    int k4 = (i4 & 31) * 4;
    const float* bias = teacher ? bt : bs;
    const float* pbase = teacher ? g_tpp : g_spp;
    int np = teacher ? 32 : 12;

    float4 a0 = *reinterpret_cast<const float4*>(&bias[k4]);
    float4 a1 = make_float4(0.f, 0.f, 0.f, 0.f);
    float4 a2 = make_float4(0.f, 0.f, 0.f, 0.f);
    float4 a3 = make_float4(0.f, 0.f, 0.f, 0.f);
    for (int p = 0; p < np; p += 4) {
        float4 v0 = *reinterpret_cast<const float4*>(&pbase[(p + 0) * (BN * HD) + i4 * 4]);
        float4 v1 = *reinterpret_cast<const float4*>(&pbase[(p + 1) * (BN * HD) + i4 * 4]);
        float4 v2 = *reinterpret_cast<const float4*>(&pbase[(p + 2) * (BN * HD) + i4 * 4]);
        float4 v3 = *reinterpret_cast<const float4*>(&pbase[(p + 3) * (BN * HD) + i4 * 4]);
        a0.x += v0.x; a0.y += v0.y; a0.z += v0.z; a0.w += v0.w;
        a1.x += v1.x; a1.y += v1.y; a1.z += v1.z; a1.w += v1.w;
        a2.x += v2.x; a2.y += v2.y; a2.z += v2.z; a2.w += v2.w;
        a3.x += v3.x; a3.y += v3.y; a3.z += v3.z; a3.w += v3.w;
    }
    float4 r = make_float4(a0.x + a1.x + a2.x + a3.x,
                           a0.y + a1.y + a2.y + a3.y,
                           a0.z + a1.z + a2.z + a3.z,
                           a0.w + a1.w + a2.w + a3.w);
    float* dst = teacher ? g_tp : g_sp;
    *reinterpret_cast<float4*>(&dst[i4 * 4]) = r;
}

// ---------------------------------------------------------------------------
// U/V projections -> TRANSPOSED outputs [h][row].
// grid (32 rowblocks of 16, 2 nets, 2 W1-halves) = 128 blocks, 128 thr.
// Tile 16r x 128c, micro 2r x 8c (col-pairs packed).
// ---------------------------------------------------------------------------
__global__ void __launch_bounds__(128)
uv_gemm(const float* __restrict__ W1, const float* __restrict__ b1) {
    const int XS = 18;
    const int WS = 132;
    __shared__ float Xst[HD * XS];                   // [k][r], 16 rows
    __shared__ __align__(16) float Wsm[32 * WS];     // [kk][c]

    int rb = blockIdx.x;
    int net = blockIdx.y;
    int half = blockIdx.z;          // 0 = U (add b1), 1 = V
    const float* X = net ? g_sp : g_tp;
    const float* W = W1 + half * HD * HD;
    float* outT = net ? (half ? g_VsT : g_UsT) : (half ? g_VtT : g_UtT);

    int tid = threadIdx.x;
    int tx = tid & 15;              // col group tx*8
    int ty = tid >> 4;              // rows ty*2..+1 (0..7)
    int r0 = rb * 16;

    // stage X transposed: 16 rows x 128 k
#pragma unroll
    for (int t = 0; t < 4; t++) {
        int i4 = tid + t * 128;
        int r = i4 >> 5, k4 = (i4 & 31) * 4;
        float4 v = *reinterpret_cast<const float4*>(&X[(r0 + r) * HD + k4]);
        Xst[(k4 + 0) * XS + r] = v.x;
        Xst[(k4 + 1) * XS + r] = v.y;
        Xst[(k4 + 2) * XS + r] = v.z;
        Xst[(k4 + 3) * XS + r] = v.w;
    }

    ull acc[2][4];                  // [row m][colpair q]
#pragma unroll
    for (int m = 0; m < 2; m++)
#pragma unroll
        for (int q = 0; q < 4; q++) acc[m][q] = 0ull;

    for (int kc = 0; kc < HD; kc += 32) {
        __syncthreads();
#pragma unroll
        for (int t = 0; t < 8; t++) {
            int i4 = tid + t * 128;
            int kk = i4 >> 5, c4 = (i4 & 31) * 4;
            *reinterpret_cast<float4*>(&Wsm[kk * WS + c4]) =
                *reinterpret_cast<const float4*>(&W[(kc + kk) * HD + c4]);
        }
        __syncthreads();
#pragma unroll 8
        for (int kk = 0; kk < 32; kk++) {
            float a0 = Xst[(kc + kk) * XS + ty * 2];
            float a1 = Xst[(kc + kk) * XS + ty * 2 + 1];
            ulonglong2 b01 = *reinterpret_cast<const ulonglong2*>(&Wsm[kk * WS + tx * 8]);
            ulonglong2 b23 = *reinterpret_cast<const ulonglong2*>(&Wsm[kk * WS + tx * 8 + 4]);
            ull ad0 = pk2(a0, a0), ad1 = pk2(a1, a1);
            fma2(acc[0][0], ad0, b01.x); fma2(acc[0][1], ad0, b01.y);
            fma2(acc[0][2], ad0, b23.x); fma2(acc[0][3], ad0, b23.y);
            fma2(acc[1][0], ad1, b01.x); fma2(acc[1][1], ad1, b01.y);
            fma2(acc[1][2], ad1, b23.x); fma2(acc[1][3], ad1, b23.y);
        }
    }

    int rbase = r0 + ty * 2;
#pragma unroll
    for (int q = 0; q < 4; q++) {
        int c = tx * 8 + q * 2;
        float2 p0 = unpk2(acc[0][q]);   // row0: cols c, c+1
        float2 p1 = unpk2(acc[1][q]);   // row1: cols c, c+1
        float bA = half ? 0.0f : b1[c];
        float bB = half ? 0.0f : b1[c + 1];
        *reinterpret_cast<float2*>(&outT[c * BN + rbase]) =
            make_float2(p0.x + bA, p1.x + bA);
        *reinterpret_cast<float2*>(&outT[(c + 1) * BN + rbase]) =
            make_float2(p0.y + bB, p1.y + bB);
    }
}

// ---------------------------------------------------------------------------
// Fused pairwise relations + sigmoid + MSE, both nets per block.
// Tile 32(i) x 16(j), grid (32 j-blocks, 16 i-blocks) = 512 blocks, 256 thr.
// Threads [0,128) = teacher, [128,256) = student; dots exchanged via smem.
// Per net-thread: micro 4i x 1j, i packed in f32x2 pairs.
// ---------------------------------------------------------------------------
__global__ void __launch_bounds__(256)
pairwise_mse(const float* __restrict__ w2, const float* __restrict__ b2v,
             float* __restrict__ out) {
    const int HB = 64;      // h chunk staged at a time
    __shared__ __align__(16) float sU[2][HB * 32];   // [net][h][i-row]
    __shared__ __align__(16) float sV[2][HB * 16];   // [net][h][j-row]
    __shared__ ull swd[HD];                          // (w/2, w/2) pairs
    __shared__ float sdot[2][32 * 16];
    __shared__ float sred[256];

    int tid = threadIdx.x;
    int net = tid >> 7;
    int tt = tid & 127;
    int jg = tt & 15;            // j = jb + jg
    int ig = tt >> 4;            // i = ib + ig*4 .. +3
    int jb = blockIdx.x * 16;
    int ib = blockIdx.y * 32;

    const float* UT = net ? g_UsT : g_UtT;
    const float* VT = net ? g_VsT : g_VtT;

    if (tid < HD) { float w = w2[tid] * 0.5f; swd[tid] = pk2(w, w); }

    ull a0 = 0ull, a1 = 0ull;    // i-pairs (ig*4+0,1) and (+2,3) for col jg

    for (int hb = 0; hb < HD; hb += HB) {
        __syncthreads();         // also covers swd init on first iter
        // stage U: 64h x 32r (512 f4 per net half, 4/thread)
#pragma unroll
        for (int t = 0; t < 4; t++) {
            int id = tt + t * 128;
            int h = id >> 3, r4 = (id & 7) * 4;
            *reinterpret_cast<float4*>(&sU[net][h * 32 + r4]) =
                *reinterpret_cast<const float4*>(&UT[(hb + h) * BN + ib + r4]);
        }
        // stage V: 64h x 16r (256 f4 per net half, 2/thread)
#pragma unroll
        for (int t = 0; t < 2; t++) {
            int id = tt + t * 128;
            int h = id >> 2, r4 = (id & 3) * 4;
            *reinterpret_cast<float4*>(&sV[net][h * 16 + r4]) =
                *reinterpret_cast<const float4*>(&VT[(hb + h) * BN + jb + r4]);
        }
        __syncthreads();
#pragma unroll 8
        for (int hh = 0; hh < HB; hh++) {
            ulonglong2 u2 = *reinterpret_cast<const ulonglong2*>(
                &sU[net][hh * 32 + ig * 4]);
            float v = sV[net][hh * 16 + jg];
            ull wd = swd[hb + hh];
            ull vd = pk2(v, v);
            rabs(a0, u2.x, vd, wd);
            rabs(a1, u2.y, vd, wd);
        }
    }

    // exchange dots
    __syncthreads();
    {
        float2 x0 = unpk2(a0);
        float2 x1 = unpk2(a1);
        int base = (ig * 4) * 16 + jg;
        sdot[net][base]          = x0.x;
        sdot[net][base + 16]     = x0.y;
        sdot[net][base + 32]     = x1.x;
        sdot[net][base + 48]     = x1.y;
    }
    __syncthreads();

    float local = 0.0f;
    if (net == 0) {
        float b2 = b2v[0];
#pragma unroll
        for (int m = 0; m < 4; m++) {
            int il = ig * 4 + m;
            if (ib + il == jb + jg) continue;   // diagonal: rel == 0 both
            float t = sdot[0][il * 16 + jg];
            float s = sdot[1][il * 16 + jg];
            float rt = 1.0f / (1.0f + __expf(-(t + b2)));
            float rs = 1.0f / (1.0f + __expf(-(s + b2)));
            float d = rs - rt;
            local = fmaf(d, d, local);
        }
    }
    sred[tid] = local;
    __syncthreads();
    for (int st = 128; st > 0; st >>= 1) {
        if (tid < st) sred[tid] += sred[tid + st];
        __syncthreads();
    }
    if (tid == 0)
        atomicAdd(out, sred[0] * (1.0f / ((float)BN * (float)BN)));
}

// ---------------------------------------------------------------------------
extern "C" void kernel_launch(void* const* d_in, const int* in_sizes, int n_in,
                              void* d_out, int out_size) {
    const float* teacher = (const float*)d_in[0];
    const float* student = (const float*)d_in[1];
    const float* Wt = (const float*)d_in[2];
    const float* bt = (const float*)d_in[3];
    const float* Wsw = (const float*)d_in[4];
    const float* bs = (const float*)d_in[5];
    const float* W1 = (const float*)d_in[6];
    const float* b1 = (const float*)d_in[7];
    const float* W2 = (const float*)d_in[8];
    const float* b2 = (const float*)d_in[9];
    float* out = (float*)d_out;

    proj_gemm<<<dim3(16, 32, 2), 128>>>(teacher, Wt, student, Wsw, out, out_size);
    sumtp<<<128, 256>>>(bt, bs);
    uv_gemm<<<dim3(32, 2, 2), 128>>>(W1, b1);
    pairwise_mse<<<dim3(32, 16), 256>>>(W2, b2, out);
}

// round 7
// speedup vs baseline: 1.1077x; 1.0243x over previous
#include <cuda_runtime.h>
#include <math.h>

#define BN 512
#define TD 2048
#define SD 768
#define HD 128

typedef unsigned long long ull;

// Scratch (device globals — no allocations allowed)
__device__ float g_tpp[32 * BN * HD];   // teacher proj partials (KLEN=64)
__device__ float g_spp[12 * BN * HD];   // student proj partials
__device__ float g_tp[BN * HD];
__device__ float g_sp[BN * HD];
// Transposed U/V: [h][row]
__device__ float g_UtT[HD * BN];
__device__ float g_VtT[HD * BN];
__device__ float g_UsT[HD * BN];
__device__ float g_VsT[HD * BN];

// ---- packed f32x2 helpers (sm_100+) --------------------------------------
__device__ __forceinline__ ull pk2(float a, float b) {
    ull r; asm("mov.b64 %0, {%1, %2};" : "=l"(r) : "f"(a), "f"(b)); return r;
}
__device__ __forceinline__ float2 unpk2(ull v) {
    float2 r; asm("mov.b64 {%0, %1}, %2;" : "=f"(r.x), "=f"(r.y) : "l"(v)); return r;
}
__device__ __forceinline__ void fma2(ull &acc, ull a, ull b) {
    asm("fma.rn.f32x2 %0, %1, %2, %0;" : "+l"(acc) : "l"(a), "l"(b));
}
// acc += relu(u + v) * w, fully packed.
// relu(x)*w = (x + |x|) * (w/2); wh pre-halved. Exact vs fl(relu(x)*w).
__device__ __forceinline__ void rabs(ull &acc, ull u, ull v, ull wh) {
    asm("{\n\t"
        ".reg .b64 t, ta;\n\t"
        "add.rn.f32x2 t, %1, %2;\n\t"
        "and.b64 ta, t, 0x7FFFFFFF7FFFFFFF;\n\t"
        "add.rn.f32x2 t, t, ta;\n\t"
        "fma.rn.f32x2 %0, t, %3, %0;\n\t"
        "}"
        : "+l"(acc) : "l"(u), "l"(v), "l"(wh));
}

// ---------------------------------------------------------------------------
// Projection GEMM partials. z=0 teacher (32 k-splits), z=1 student (12).
// KLEN=64, KC=32. Block: 32 rows x 128 cols, 128 threads, micro 4r x 8c.
// Also zeroes the output scalar (block (0,0,0)).
// ---------------------------------------------------------------------------
__global__ void __launch_bounds__(128)
proj_gemm(const float* __restrict__ T, const float* __restrict__ Wt,
          const float* __restrict__ S, const float* __restrict__ Ws,
          float* __restrict__ out, int out_size) {
    const int KC = 32;
    const int XP = 36;
    __shared__ __align__(16) float Xst[KC * XP];      // [k][r] transposed
    __shared__ __align__(16) float Wsm[KC * HD];      // [kk][c]

    if (blockIdx.x == 0 && blockIdx.y == 0 && blockIdx.z == 0 && threadIdx.x == 0)
        for (int i = 0; i < out_size; i++) out[i] = 0.0f;

    int z = blockIdx.z;
    int ky = blockIdx.y;
    const float* X; const float* W; float* outp; int ldx;
    if (z == 0) { X = T; W = Wt; ldx = TD; outp = g_tpp + ky * (BN * HD); }
    else {
        if (ky >= 12) return;
        X = S; W = Ws; ldx = SD; outp = g_spp + ky * (BN * HD);
    }

    int tid = threadIdx.x;        // 128
    int tx = tid & 15;            // cols tx*8..+7
    int ty = tid >> 4;            // rows ty*4..+3
    int row0 = blockIdx.x * 32;
    int k0 = ky * 64;

    ull acc[4][4];                // [colpair q][row m]
#pragma unroll
    for (int q = 0; q < 4; q++)
#pragma unroll
        for (int m = 0; m < 4; m++) acc[q][m] = 0ull;

#pragma unroll
    for (int kc = 0; kc < 64; kc += KC) {
#pragma unroll
        for (int t = 0; t < 2; t++) {
            int i4 = tid + t * 128;
            int r = i4 >> 3, k4 = (i4 & 7) * 4;
            float4 v = *reinterpret_cast<const float4*>(
                &X[(row0 + r) * ldx + k0 + kc + k4]);
            Xst[(k4 + 0) * XP + r] = v.x;
            Xst[(k4 + 1) * XP + r] = v.y;
            Xst[(k4 + 2) * XP + r] = v.z;
            Xst[(k4 + 3) * XP + r] = v.w;
        }
#pragma unroll
        for (int t = 0; t < 8; t++) {
            int i4 = tid + t * 128;
            int kk = i4 >> 5, c4 = (i4 & 31) * 4;
            float4 v = *reinterpret_cast<const float4*>(
                &W[(k0 + kc + kk) * HD + c4]);
            *reinterpret_cast<float4*>(&Wsm[kk * HD + c4]) = v;
        }
        __syncthreads();
#pragma unroll 8
        for (int kk = 0; kk < KC; kk++) {
            float4 a4 = *reinterpret_cast<const float4*>(&Xst[kk * XP + ty * 4]);
            ulonglong2 b01 = *reinterpret_cast<const ulonglong2*>(&Wsm[kk * HD + tx * 8]);
            ulonglong2 b23 = *reinterpret_cast<const ulonglong2*>(&Wsm[kk * HD + tx * 8 + 4]);
            ull a0 = pk2(a4.x, a4.x), a1 = pk2(a4.y, a4.y);
            ull a2 = pk2(a4.z, a4.z), a3 = pk2(a4.w, a4.w);
            fma2(acc[0][0], a0, b01.x); fma2(acc[0][1], a1, b01.x);
            fma2(acc[0][2], a2, b01.x); fma2(acc[0][3], a3, b01.x);
            fma2(acc[1][0], a0, b01.y); fma2(acc[1][1], a1, b01.y);
            fma2(acc[1][2], a2, b01.y); fma2(acc[1][3], a3, b01.y);
            fma2(acc[2][0], a0, b23.x); fma2(acc[2][1], a1, b23.x);
            fma2(acc[2][2], a2, b23.x); fma2(acc[2][3], a3, b23.x);
            fma2(acc[3][0], a0, b23.y); fma2(acc[3][1], a1, b23.y);
            fma2(acc[3][2], a2, b23.y); fma2(acc[3][3], a3, b23.y);
        }
        __syncthreads();
    }
#pragma unroll
    for (int m = 0; m < 4; m++) {
        int row = row0 + ty * 4 + m;
        float2 q0 = unpk2(acc[0][m]);
        float2 q1 = unpk2(acc[1][m]);
        float2 q2 = unpk2(acc[2][m]);
        float2 q3 = unpk2(acc[3][m]);
        *reinterpret_cast<float4*>(&outp[row * HD + tx * 8]) =
            make_float4(q0.x, q0.y, q1.x, q1.y);
        *reinterpret_cast<float4*>(&outp[row * HD + tx * 8 + 4]) =
            make_float4(q2.x, q2.y, q3.x, q3.y);
    }
}

// ---------------------------------------------------------------------------
// Sum proj partials + bias -> g_tp / g_sp. Grid 128 x 256 thr.
// ---------------------------------------------------------------------------
__global__ void __launch_bounds__(256)
sumtp(const float* __restrict__ bt, const float* __restrict__ bs) {
    int b = blockIdx.x;
    int teacher = (b < 64);
    int i4 = (teacher ? b : b - 64) * 256 + threadIdx.x;
    int k4 = (i4 & 31) * 4;
    const float* bias = teacher ? bt : bs;
    const float* pbase = teacher ? g_tpp : g_spp;
    int np = teacher ? 32 : 12;

    float4 a0 = *reinterpret_cast<const float4*>(&bias[k4]);
    float4 a1 = make_float4(0.f, 0.f, 0.f, 0.f);
    float4 a2 = make_float4(0.f, 0.f, 0.f, 0.f);
    float4 a3 = make_float4(0.f, 0.f, 0.f, 0.f);
    for (int p = 0; p < np; p += 4) {
        float4 v0 = *reinterpret_cast<const float4*>(&pbase[(p + 0) * (BN * HD) + i4 * 4]);
        float4 v1 = *reinterpret_cast<const float4*>(&pbase[(p + 1) * (BN * HD) + i4 * 4]);
        float4 v2 = *reinterpret_cast<const float4*>(&pbase[(p + 2) * (BN * HD) + i4 * 4]);
        float4 v3 = *reinterpret_cast<const float4*>(&pbase[(p + 3) * (BN * HD) + i4 * 4]);
        a0.x += v0.x; a0.y += v0.y; a0.z += v0.z; a0.w += v0.w;
        a1.x += v1.x; a1.y += v1.y; a1.z += v1.z; a1.w += v1.w;
        a2.x += v2.x; a2.y += v2.y; a2.z += v2.z; a2.w += v2.w;
        a3.x += v3.x; a3.y += v3.y; a3.z += v3.z; a3.w += v3.w;
    }
    float4 r = make_float4(a0.x + a1.x + a2.x + a3.x,
                           a0.y + a1.y + a2.y + a3.y,
                           a0.z + a1.z + a2.z + a3.z,
                           a0.w + a1.w + a2.w + a3.w);
    float* dst = teacher ? g_tp : g_sp;
    *reinterpret_cast<float4*>(&dst[i4 * 4]) = r;
}

// ---------------------------------------------------------------------------
// U/V projections -> TRANSPOSED outputs [h][row].
// grid (32 rowblocks of 16, 2 nets, 2 W1-halves) = 128 blocks, 128 thr.
// ---------------------------------------------------------------------------
__global__ void __launch_bounds__(128)
uv_gemm(const float* __restrict__ W1, const float* __restrict__ b1) {
    const int XS = 18;
    const int WS = 132;
    __shared__ float Xst[HD * XS];                   // [k][r], 16 rows
    __shared__ __align__(16) float Wsm[32 * WS];     // [kk][c]

    int rb = blockIdx.x;
    int net = blockIdx.y;
    int half = blockIdx.z;          // 0 = U (add b1), 1 = V
    const float* X = net ? g_sp : g_tp;
    const float* W = W1 + half * HD * HD;
    float* outT = net ? (half ? g_VsT : g_UsT) : (half ? g_VtT : g_UtT);

    int tid = threadIdx.x;
    int tx = tid & 15;
    int ty = tid >> 4;
    int r0 = rb * 16;

#pragma unroll
    for (int t = 0; t < 4; t++) {
        int i4 = tid + t * 128;
        int r = i4 >> 5, k4 = (i4 & 31) * 4;
        float4 v = *reinterpret_cast<const float4*>(&X[(r0 + r) * HD + k4]);
        Xst[(k4 + 0) * XS + r] = v.x;
        Xst[(k4 + 1) * XS + r] = v.y;
        Xst[(k4 + 2) * XS + r] = v.z;
        Xst[(k4 + 3) * XS + r] = v.w;
    }

    ull acc[2][4];
#pragma unroll
    for (int m = 0; m < 2; m++)
#pragma unroll
        for (int q = 0; q < 4; q++) acc[m][q] = 0ull;

    for (int kc = 0; kc < HD; kc += 32) {
        __syncthreads();
#pragma unroll
        for (int t = 0; t < 8; t++) {
            int i4 = tid + t * 128;
            int kk = i4 >> 5, c4 = (i4 & 31) * 4;
            *reinterpret_cast<float4*>(&Wsm[kk * WS + c4]) =
                *reinterpret_cast<const float4*>(&W[(kc + kk) * HD + c4]);
        }
        __syncthreads();
#pragma unroll 8
        for (int kk = 0; kk < 32; kk++) {
            float a0 = Xst[(kc + kk) * XS + ty * 2];
            float a1 = Xst[(kc + kk) * XS + ty * 2 + 1];
            ulonglong2 b01 = *reinterpret_cast<const ulonglong2*>(&Wsm[kk * WS + tx * 8]);
            ulonglong2 b23 = *reinterpret_cast<const ulonglong2*>(&Wsm[kk * WS + tx * 8 + 4]);
            ull ad0 = pk2(a0, a0), ad1 = pk2(a1, a1);
            fma2(acc[0][0], ad0, b01.x); fma2(acc[0][1], ad0, b01.y);
            fma2(acc[0][2], ad0, b23.x); fma2(acc[0][3], ad0, b23.y);
            fma2(acc[1][0], ad1, b01.x); fma2(acc[1][1], ad1, b01.y);
            fma2(acc[1][2], ad1, b23.x); fma2(acc[1][3], ad1, b23.y);
        }
    }

    int rbase = r0 + ty * 2;
#pragma unroll
    for (int q = 0; q < 4; q++) {
        int c = tx * 8 + q * 2;
        float2 p0 = unpk2(acc[0][q]);
        float2 p1 = unpk2(acc[1][q]);
        float bA = half ? 0.0f : b1[c];
        float bB = half ? 0.0f : b1[c + 1];
        *reinterpret_cast<float2*>(&outT[c * BN + rbase]) =
            make_float2(p0.x + bA, p1.x + bA);
        *reinterpret_cast<float2*>(&outT[(c + 1) * BN + rbase]) =
            make_float2(p0.y + bB, p1.y + bB);
    }
}

// ---------------------------------------------------------------------------
// Fused pairwise relations + sigmoid + MSE, both nets per block.
// Tile 32(i) x 32(j), grid (16, 16) = 256 blocks, 256 thr.
// Threads [0,128) = teacher, [128,256) = student; micro 4i x 2j.
// V staged pre-duplicated as packed (v,v) ull pairs -> mov-free inner loop.
// ---------------------------------------------------------------------------
__global__ void __launch_bounds__(256)
pairwise_mse(const float* __restrict__ w2, const float* __restrict__ b2v,
             float* __restrict__ out) {
    const int HB = 32;      // h chunk
    __shared__ __align__(16) float sU[2][HB * 32];   // [net][h][i-row]
    __shared__ __align__(16) ull sVd[2][HB * 32];    // [net][h][j] dup-packed
    __shared__ ull swd[HD];                          // (w/2, w/2)
    __shared__ float sdot[2][32 * 32];
    __shared__ float sred[256];

    int tid = threadIdx.x;
    int net = tid >> 7;
    int tt = tid & 127;
    int tx = tt & 15;            // j = jb + tx*2 + {0,1}
    int ty = tt >> 4;            // i = ib + ty*4 + {0..3}
    int jb = blockIdx.x * 32;
    int ib = blockIdx.y * 32;

    const float* UT = net ? g_UsT : g_UtT;
    const float* VT = net ? g_VsT : g_VtT;

    if (tid < HD) { float w = w2[tid] * 0.5f; swd[tid] = pk2(w, w); }

    ull a00 = 0ull, a01 = 0ull, a10 = 0ull, a11 = 0ull;

    for (int hb = 0; hb < HD; hb += HB) {
        __syncthreads();
        // stage U: 32h x 32r (256 f4 per net, 2/thread)
#pragma unroll
        for (int t = 0; t < 2; t++) {
            int id = tt + t * 128;
            int h = id >> 3, r4 = (id & 7) * 4;
            *reinterpret_cast<float4*>(&sU[net][h * 32 + r4]) =
                *reinterpret_cast<const float4*>(&UT[(hb + h) * BN + ib + r4]);
        }
        // stage V dup-packed: 32h x 32j (2 f4/thread -> 4 STS.128)
#pragma unroll
        for (int t = 0; t < 2; t++) {
            int id = tt + t * 128;
            int h = id >> 3, c4 = (id & 7) * 4;
            float4 v = *reinterpret_cast<const float4*>(&VT[(hb + h) * BN + jb + c4]);
            ulonglong2 p0, p1;
            p0.x = pk2(v.x, v.x); p0.y = pk2(v.y, v.y);
            p1.x = pk2(v.z, v.z); p1.y = pk2(v.w, v.w);
            *reinterpret_cast<ulonglong2*>(&sVd[net][h * 32 + c4]) = p0;
            *reinterpret_cast<ulonglong2*>(&sVd[net][h * 32 + c4 + 2]) = p1;
        }
        __syncthreads();
#pragma unroll 8
        for (int hh = 0; hh < HB; hh++) {
            ulonglong2 u2 = *reinterpret_cast<const ulonglong2*>(
                &sU[net][hh * 32 + ty * 4]);
            ulonglong2 vd = *reinterpret_cast<const ulonglong2*>(
                &sVd[net][hh * 32 + tx * 2]);
            ull wd = swd[hb + hh];
            rabs(a00, u2.x, vd.x, wd);
            rabs(a01, u2.y, vd.x, wd);
            rabs(a10, u2.x, vd.y, wd);
            rabs(a11, u2.y, vd.y, wd);
        }
    }

    // exchange dots
    __syncthreads();
    {
        int il = ty * 4, jl = tx * 2;
        float2 x;
        x = unpk2(a00); sdot[net][(il + 0) * 32 + jl] = x.x;
                        sdot[net][(il + 1) * 32 + jl] = x.y;
        x = unpk2(a01); sdot[net][(il + 2) * 32 + jl] = x.x;
                        sdot[net][(il + 3) * 32 + jl] = x.y;
        x = unpk2(a10); sdot[net][(il + 0) * 32 + jl + 1] = x.x;
                        sdot[net][(il + 1) * 32 + jl + 1] = x.y;
        x = unpk2(a11); sdot[net][(il + 2) * 32 + jl + 1] = x.x;
                        sdot[net][(il + 3) * 32 + jl + 1] = x.y;
    }
    __syncthreads();

    float local = 0.0f;
    if (net == 0) {
        float b2 = b2v[0];
#pragma unroll
        for (int m = 0; m < 4; m++) {
#pragma unroll
            for (int n = 0; n < 2; n++) {
                int il = ty * 4 + m, jl = tx * 2 + n;
                if (ib + il == jb + jl) continue;   // diagonal: rel == 0 both
                float t = sdot[0][il * 32 + jl];
                float s = sdot[1][il * 32 + jl];
                float rt = 1.0f / (1.0f + __expf(-(t + b2)));
                float rs = 1.0f / (1.0f + __expf(-(s + b2)));
                float d = rs - rt;
                local = fmaf(d, d, local);
            }
        }
    }
    sred[tid] = local;
    __syncthreads();
    for (int st = 128; st > 0; st >>= 1) {
        if (tid < st) sred[tid] += sred[tid + st];
        __syncthreads();
    }
    if (tid == 0)
        atomicAdd(out, sred[0] * (1.0f / ((float)BN * (float)BN)));
}

// ---------------------------------------------------------------------------
extern "C" void kernel_launch(void* const* d_in, const int* in_sizes, int n_in,
                              void* d_out, int out_size) {
    const float* teacher = (const float*)d_in[0];
    const float* student = (const float*)d_in[1];
    const float* Wt = (const float*)d_in[2];
    const float* bt = (const float*)d_in[3];
    const float* Wsw = (const float*)d_in[4];
    const float* bs = (const float*)d_in[5];
    const float* W1 = (const float*)d_in[6];
    const float* b1 = (const float*)d_in[7];
    const float* W2 = (const float*)d_in[8];
    const float* b2 = (const float*)d_in[9];
    float* out = (float*)d_out;

    proj_gemm<<<dim3(16, 32, 2), 128>>>(teacher, Wt, student, Wsw, out, out_size);
    sumtp<<<128, 256>>>(bt, bs);
    uv_gemm<<<dim3(32, 2, 2), 128>>>(W1, b1);
    pairwise_mse<<<dim3(16, 16), 256>>>(W2, b2, out);
}